// round 8
// baseline (speedup 1.0000x reference)
#include <cuda_runtime.h>
#include <cstdint>
#include <math.h>

#define Dm 1024
#define Hn 8
#define DHn 128
#define Fn 4096
#define Vn 16384
#define ENCn 438
#define PASTn 447
#define Lnum 8
#define NSPLIT 32
#define SPLEN 14
#define NB 296
#define ATT_SCALE 0.08838834764831845f

// ---------------- device scratch ----------------
__device__ float g_x[Dm];            // residual stream (atomic accumulated)
__device__ float A_qkv[3 * Dm];      // atomic acc
__device__ float A_qc[Dm];           // atomic acc
__device__ float A_u[Hn * Dm];       // atomic acc
__device__ float A_o2[Dm];           // atomic acc
__device__ float A_ffn[Fn];          // atomic acc
__device__ float g_t[Hn * Dm];
__device__ float g_sc[Hn * ENCn];
__device__ float g_po[Hn * NSPLIT * DHn];
__device__ float g_pm[Hn * NSPLIT];
__device__ float g_ps[Hn * NSPLIT];
__device__ int g_cnt;
__device__ volatile int g_gen;

__device__ __forceinline__ float gelu_f(float v) {
    float c = v * v * v;
    return 0.5f * v * (1.0f + tanhf(0.7978845608028654f * (v + 0.044715f * c)));
}
__device__ __forceinline__ float ldg1(const float* p) { return __ldcg(p); }
__device__ __forceinline__ float4 ldg4(const float* p) { return __ldcg((const float4*)p); }

// fire-and-forget L2 prefetch of nf floats, spread over all NB blocks
__device__ __forceinline__ void pf_range(const float* base, size_t nf) {
    size_t lines = nf >> 5;  // 128B lines
    size_t per = (lines + NB - 1) / NB;
    size_t i0 = (size_t)blockIdx.x * per;
    size_t i1 = i0 + per;
    if (i1 > lines) i1 = lines;
    for (size_t i = i0 + threadIdx.x; i < i1; i += 256)
        asm volatile("prefetch.global.L2 [%0];" :: "l"(base + (i << 5)));
}

// global software barrier (generation-based; replay-safe)
__device__ __forceinline__ void gbar() {
    __syncthreads();
    if (threadIdx.x == 0) {
        __threadfence();
        int gen = g_gen;
        if (atomicAdd(&g_cnt, 1) == NB - 1) {
            g_cnt = 0;
            __threadfence();
            g_gen = gen + 1;
        } else {
            while (g_gen == gen) { __nanosleep(32); }
        }
    }
    __syncthreads();
}

// one block zeroes 1024 floats
__device__ __forceinline__ void zero1k(float* base) {
    ((float4*)base)[threadIdx.x] = make_float4(0.f, 0.f, 0.f, 0.f);
}

// coalesced matvec core; atomicAdd partial into dst[grp*128 .. +128)
__device__ __forceinline__ void mv_core(const float* __restrict__ W, int dout4,
                                        int grp, int r0, int r1,
                                        const float* sxp,
                                        float* __restrict__ dst,
                                        float4 (*s_acc)[32]) {
    int tid = threadIdx.x, w = tid >> 5, lane = tid & 31;
    const float4* W4 = (const float4*)W;
    int q = grp * 32 + lane;
    float4 acc = make_float4(0.f, 0.f, 0.f, 0.f);
    #pragma unroll 8
    for (int r = r0 + w; r < r1; r += 8) {
        float xv = sxp[r - r0];
        float4 wv = W4[(size_t)r * dout4 + q];
        acc.x += xv * wv.x; acc.y += xv * wv.y;
        acc.z += xv * wv.z; acc.w += xv * wv.w;
    }
    s_acc[w][lane] = acc;
    __syncthreads();
    if (tid < 32) {
        float4 t = s_acc[0][tid];
        #pragma unroll
        for (int i = 1; i < 8; i++) {
            float4 a = s_acc[i][tid];
            t.x += a.x; t.y += a.y; t.z += a.z; t.w += a.w;
        }
        float* op = dst + grp * 128 + tid * 4;
        atomicAdd(op + 0, t.x);
        atomicAdd(op + 1, t.y);
        atomicAdd(op + 2, t.z);
        atomicAdd(op + 3, t.w);
    }
    __syncthreads();
}

// LN of g_x -> sx[0..1023]
__device__ __forceinline__ void ln_simple(const float* __restrict__ gamma,
                                          const float* __restrict__ beta,
                                          float* sx, float* swr) {
    int tid = threadIdx.x, w = tid >> 5, lane = tid & 31;
    float4 xv = ldg4(g_x + tid * 4);
    float s = xv.x + xv.y + xv.z + xv.w;
    #pragma unroll
    for (int m = 16; m >= 1; m >>= 1) s += __shfl_xor_sync(0xffffffffu, s, m);
    if (lane == 0) swr[w] = s;
    __syncthreads();
    float mean = 0.0f;
    #pragma unroll
    for (int i = 0; i < 8; i++) mean += swr[i];
    mean *= (1.0f / 1024.0f);
    float4 dv;
    dv.x = xv.x - mean; dv.y = xv.y - mean; dv.z = xv.z - mean; dv.w = xv.w - mean;
    float s2 = dv.x * dv.x + dv.y * dv.y + dv.z * dv.z + dv.w * dv.w;
    #pragma unroll
    for (int m = 16; m >= 1; m >>= 1) s2 += __shfl_xor_sync(0xffffffffu, s2, m);
    __syncthreads();
    if (lane == 0) swr[w] = s2;
    __syncthreads();
    float var = 0.0f;
    #pragma unroll
    for (int i = 0; i < 8; i++) var += swr[i];
    float rstd = rsqrtf(var * (1.0f / 1024.0f) + 1e-5f);
    float4 g4 = ((const float4*)gamma)[tid];
    float4 b4 = ((const float4*)beta)[tid];
    float4 o;
    o.x = dv.x * rstd * g4.x + b4.x;
    o.y = dv.y * rstd * g4.y + b4.y;
    o.z = dv.z * rstd * g4.z + b4.z;
    o.w = dv.w * rstd * g4.w + b4.w;
    ((float4*)sx)[tid] = o;
    __syncthreads();
}

__global__ void __launch_bounds__(256, 2)
mega(const int* __restrict__ ids, const float* __restrict__ enc,
     const float* __restrict__ past_k, const float* __restrict__ past_v,
     const float* __restrict__ emb, const float* __restrict__ pos,
     const float* __restrict__ ln1_g, const float* __restrict__ ln1_b,
     const float* __restrict__ wq_s, const float* __restrict__ wk_s,
     const float* __restrict__ wv_s, const float* __restrict__ wo_s,
     const float* __restrict__ ln2_g, const float* __restrict__ ln2_b,
     const float* __restrict__ wq_c, const float* __restrict__ wk_c,
     const float* __restrict__ wv_c, const float* __restrict__ wo_c,
     const float* __restrict__ ln3_g, const float* __restrict__ ln3_b,
     const float* __restrict__ w1, const float* __restrict__ w2,
     const float* __restrict__ lnf_g, const float* __restrict__ lnf_b,
     float* __restrict__ out) {
    __shared__ float sx[8192];
    __shared__ float4 s_acc[8][32];
    __shared__ float swr[8];
    __shared__ float sms[2];
    int bid = blockIdx.x, tid = threadIdx.x, w = tid >> 5, lane = tid & 31;
    const size_t DD = (size_t)Dm * Dm;
    const size_t DF = (size_t)Dm * Fn;
    const size_t KVL = (size_t)Hn * PASTn * DHn;
    const size_t P = (size_t)Vn * Dm, P3 = P / 3;

    // ---- embed + zero all accumulators + prefetch S1(l=0) ----
    if (bid == 0) {
        int id = ids[0];
        float4 a = *(const float4*)(emb + (size_t)id * Dm + tid * 4);
        float4 b = *(const float4*)(pos + (size_t)PASTn * Dm + tid * 4);
        a.x += b.x; a.y += b.y; a.z += b.z; a.w += b.w;
        ((float4*)g_x)[tid] = a;
    } else if (bid <= 17) {
        int seg = bid - 1;
        if (seg < 3) zero1k(A_qkv + seg * 1024);
        else if (seg == 3) zero1k(A_qc);
        else if (seg < 12) zero1k(A_u + (seg - 4) * 1024);
        else if (seg == 12) zero1k(A_o2);
        else zero1k(A_ffn + (seg - 13) * 1024);
    }
    pf_range(wq_s, DD); pf_range(wk_s, DD); pf_range(wv_s, DD);
    gbar();

    for (int l = 0; l < Lnum; l++) {
        const float* pk = past_k + (size_t)l * KVL;
        const float* pv = past_v + (size_t)l * KVL;
        // ---- S1: LN1 + qkv (288 blocks) ----
        if (bid < 288) {
            int m = bid / 96, rem = bid % 96, grp = rem / 12, rs = rem % 12;
            int r0 = (rs * 1024) / 12, r1 = ((rs + 1) * 1024) / 12;
            ln_simple(ln1_g + l * Dm, ln1_b + l * Dm, sx, swr);
            const float* W = (m == 0 ? wq_s : (m == 1 ? wk_s : wv_s)) + l * DD;
            mv_core(W, 256, grp, r0, r1, sx + r0, A_qkv + m * Dm, s_acc);
        }
        pf_range(wo_s + l * DD, DD); pf_range(pk, KVL); pf_range(pv, KVL);
        gbar();
        // ---- S2: split-KV self attention (256) + zero A_ffn ----
        if (bid < 256) {
            int h = bid >> 5, split = bid & 31, base = split * SPLEN;
            for (int i = tid; i < 384; i += 256) {
                int vec = i >> 7, c = i & 127;
                sx[i] = ldg1(A_qkv + vec * Dm + h * DHn + c);
            }
            __syncthreads();
            for (int pp = w; pp < SPLEN; pp += 8) {
                int p = base + pp;
                float4 k4 = (p < PASTn)
                    ? *(const float4*)(pk + ((size_t)h * PASTn + p) * DHn + lane * 4)
                    : ((float4*)(sx + 128))[lane];
                float4 q4 = ((float4*)sx)[lane];
                float d = k4.x * q4.x + k4.y * q4.y + k4.z * q4.z + k4.w * q4.w;
                #pragma unroll
                for (int m2 = 16; m2 >= 1; m2 >>= 1)
                    d += __shfl_xor_sync(0xffffffffu, d, m2);
                if (lane == 0) sx[384 + pp] = d * ATT_SCALE;
            }
            __syncthreads();
            if (tid < 32) {
                float v = (lane < SPLEN) ? sx[384 + lane] : -1e30f;
                float mm = v;
                #pragma unroll
                for (int m2 = 16; m2 >= 1; m2 >>= 1)
                    mm = fmaxf(mm, __shfl_xor_sync(0xffffffffu, mm, m2));
                float e = (lane < SPLEN) ? expf(v - mm) : 0.0f;
                float s = e;
                #pragma unroll
                for (int m2 = 16; m2 >= 1; m2 >>= 1)
                    s += __shfl_xor_sync(0xffffffffu, s, m2);
                if (lane < SPLEN) sx[384 + lane] = e;
                if (lane == 0) { sms[0] = mm; sms[1] = s; }
            }
            __syncthreads();
            int c = tid & 127, ph = tid >> 7;
            float acc = 0.0f;
            #pragma unroll
            for (int k = 0; k < 7; k++) {
                int pp = ph * 7 + k;
                int p = base + pp;
                float vv = (p < PASTn)
                    ? pv[((size_t)h * PASTn + p) * DHn + c] : sx[256 + c];
                acc += sx[384 + pp] * vv;
            }
            sx[512 + tid] = acc;
            __syncthreads();
            if (tid < 128) {
                g_po[(h * NSPLIT + split) * DHn + tid] = sx[512 + tid] + sx[640 + tid];
                if (tid == 0) {
                    g_pm[h * NSPLIT + split] = sms[0];
                    g_ps[h * NSPLIT + split] = sms[1];
                }
            }
        } else if (bid < 260) {
            zero1k(A_ffn + (bid - 256) * 1024);
        }
        pf_range(wq_c + l * DD, DD);
        gbar();
        // ---- S3: combine + wo_s -> x (256) + zero A_qkv ----
        if (bid < 256) {
            int grp = bid >> 5, rs = bid & 31, r0 = rs * 32;
            int h = rs >> 2, c0 = (rs & 3) * 32;
            if (tid < 32) {
                sx[256 + tid] = ldg1(g_pm + h * NSPLIT + tid);
                sx[288 + tid] = ldg1(g_ps + h * NSPLIT + tid);
            }
            __syncthreads();
            if (tid < 32) {
                float M = -1e30f;
                #pragma unroll
                for (int s = 0; s < NSPLIT; s++) M = fmaxf(M, sx[256 + s]);
                float S = 0.0f, o = 0.0f;
                #pragma unroll
                for (int s = 0; s < NSPLIT; s++) {
                    float wv = expf(sx[256 + s] - M);
                    S += sx[288 + s] * wv;
                    o += ldg1(g_po + (h * NSPLIT + s) * DHn + c0 + tid) * wv;
                }
                sx[tid] = o / S;
            }
            __syncthreads();
            mv_core(wo_s + l * DD, 256, grp, r0, r0 + 32, sx, g_x, s_acc);
        } else if (bid < 259) {
            zero1k(A_qkv + (bid - 256) * 1024);
        }
        pf_range(wk_c + l * DD, DD);
        gbar();
        // ---- S4: LN2 + qc (256) ----
        if (bid < 256) {
            ln_simple(ln2_g + l * Dm, ln2_b + l * Dm, sx, swr);
            int grp = bid >> 5, rs = bid & 31, r0 = rs * 32;
            mv_core(wq_c + l * DD, 256, grp, r0, r0 + 32, sx + r0, A_qc, s_acc);
        }
        pf_range(enc, (size_t)ENCn * Dm);
        gbar();
        // ---- S5: t (128 blocks, warp per wk row) ----
        if (bid < 128) {
            ((float4*)sx)[tid] = ldg4(A_qc + tid * 4);
            __syncthreads();
            int d = bid * 8 + w;
            const float4* row = (const float4*)(wk_c + l * DD + (size_t)d * Dm);
            float acc[Hn];
            #pragma unroll
            for (int h = 0; h < Hn; h++) {
                float4 w4 = row[h * 32 + lane];
                float4 q4 = ((float4*)sx)[h * 32 + lane];
                acc[h] = w4.x * q4.x + w4.y * q4.y + w4.z * q4.z + w4.w * q4.w;
            }
            #pragma unroll
            for (int h = 0; h < Hn; h++) {
                #pragma unroll
                for (int m2 = 16; m2 >= 1; m2 >>= 1)
                    acc[h] += __shfl_xor_sync(0xffffffffu, acc[h], m2);
            }
            if (lane == 0) {
                #pragma unroll
                for (int h = 0; h < Hn; h++) g_t[h * Dm + d] = acc[h];
            }
        }
        pf_range(wv_c + l * DD, DD);
        gbar();
        // ---- S6: cross scores (55) + zero A_qc ----
        if (bid < 55) {
            for (int i = tid; i < 2048; i += 256) ((float4*)sx)[i] = ldg4(g_t + i * 4);
            __syncthreads();
            int e = bid * 8 + w;
            if (e < ENCn) {
                const float4* erow = (const float4*)(enc + (size_t)e * Dm);
                float acc[Hn];
                #pragma unroll
                for (int h = 0; h < Hn; h++) acc[h] = 0.0f;
                #pragma unroll
                for (int r = 0; r < 8; r++) {
                    float4 e4 = erow[r * 32 + lane];
                    #pragma unroll
                    for (int h = 0; h < Hn; h++) {
                        float4 t4 = ((float4*)sx)[h * 256 + r * 32 + lane];
                        acc[h] += e4.x * t4.x + e4.y * t4.y + e4.z * t4.z + e4.w * t4.w;
                    }
                }
                #pragma unroll
                for (int h = 0; h < Hn; h++) {
                    #pragma unroll
                    for (int m2 = 16; m2 >= 1; m2 >>= 1)
                        acc[h] += __shfl_xor_sync(0xffffffffu, acc[h], m2);
                }
                if (lane == 0) {
                    #pragma unroll
                    for (int h = 0; h < Hn; h++)
                        g_sc[h * ENCn + e] = acc[h] * ATT_SCALE;
                }
            }
        } else if (bid == 55) {
            zero1k(A_qc);
        }
        pf_range(wo_c + l * DD, DD);
        gbar();
        // ---- S7: softmax + u (256) ----
        if (bid < 256) {
            int head = bid >> 5, rem = bid & 31, grp = rem >> 2, rs = rem & 3;
            int ub0 = rs * 110, ub1 = (rs == 3) ? ENCn : ub0 + 110;
            const float* scp = g_sc + head * ENCn;
            float v0 = (tid < ENCn) ? ldg1(scp + tid) : -1e30f;
            float v1 = (tid + 256 < ENCn) ? ldg1(scp + tid + 256) : -1e30f;
            float m = fmaxf(v0, v1);
            #pragma unroll
            for (int m2 = 16; m2 >= 1; m2 >>= 1)
                m = fmaxf(m, __shfl_xor_sync(0xffffffffu, m, m2));
            if (lane == 0) swr[w] = m;
            __syncthreads();
            float M = swr[0];
            #pragma unroll
            for (int i = 1; i < 8; i++) M = fmaxf(M, swr[i]);
            float e0 = (tid < ENCn) ? expf(v0 - M) : 0.0f;
            float e1 = (tid + 256 < ENCn) ? expf(v1 - M) : 0.0f;
            float s = e0 + e1;
            #pragma unroll
            for (int m2 = 16; m2 >= 1; m2 >>= 1)
                s += __shfl_xor_sync(0xffffffffu, s, m2);
            __syncthreads();
            if (lane == 0) swr[w] = s;
            __syncthreads();
            float S = 0.0f;
            #pragma unroll
            for (int i = 0; i < 8; i++) S += swr[i];
            float inv = 1.0f / S;
            for (int i = tid; i < ub1 - ub0; i += 256)
                sx[i] = expf(ldg1(scp + ub0 + i) - M) * inv;
            __syncthreads();
            mv_core(enc, 256, grp, ub0, ub1, sx, A_u + head * Dm, s_acc);
        }
        pf_range(w1 + l * DF, DF);
        gbar();
        // ---- S8: u @ wv_c -> A_o2 (256) ----
        if (bid < 256) {
            int grp = bid >> 5, rs = bid & 31, r0 = rs * 32;
            if (tid < 32) sx[tid] = ldg1(A_u + grp * Dm + r0 + tid);
            __syncthreads();
            mv_core(wv_c + l * DD, 256, grp, r0, r0 + 32, sx, A_o2, s_acc);
        }
        pf_range(w2 + l * DF, DF);
        gbar();
        // ---- S9: o2 @ wo_c -> x (256) + zero A_u ----
        if (bid < 256) {
            int grp = bid >> 5, rs = bid & 31, r0 = rs * 32;
            if (tid < 32) sx[tid] = ldg1(A_o2 + r0 + tid);
            __syncthreads();
            mv_core(wo_c + l * DD, 256, grp, r0, r0 + 32, sx, g_x, s_acc);
        } else if (bid < 264) {
            zero1k(A_u + (bid - 256) * 1024);
        }
        if (l == Lnum - 1) pf_range(emb, P3);
        gbar();
        // ---- S10: LN3 + w1 -> A_ffn (288) + zero A_o2 ----
        if (bid < 288) {
            ln_simple(ln3_g + l * Dm, ln3_b + l * Dm, sx, swr);
            int grp = bid / 9, rs = bid % 9;
            int r0 = (rs * 1024) / 9, r1 = ((rs + 1) * 1024) / 9;
            mv_core(w1 + l * DF, 1024, grp, r0, r1, sx + r0, A_ffn, s_acc);
        } else if (bid == 288) {
            zero1k(A_o2);
        }
        if (l < Lnum - 1) {
            pf_range(wq_s + (l + 1) * DD, DD);
            pf_range(wk_s + (l + 1) * DD, DD);
        } else {
            pf_range(emb + P3, P3);
        }
        gbar();
        // ---- S11: gelu(ffn) @ w2 -> x (256) ----
        if (bid < 256) {
            int grp = bid >> 5, rs = bid & 31, r0 = rs * 128;
            if (tid < 128) sx[tid] = gelu_f(ldg1(A_ffn + r0 + tid));
            __syncthreads();
            mv_core(w2 + l * DF, 256, grp, r0, r0 + 128, sx, g_x, s_acc);
        }
        if (l < Lnum - 1) pf_range(wv_s + (l + 1) * DD, DD);
        else pf_range(emb + 2 * P3, P - 2 * P3);
        gbar();
    }

    // ---- final LN + tied lm_head ----
    ln_simple(lnf_g, lnf_b, sx, swr);
    for (int v = bid * 8 + w; v < Vn; v += NB * 8) {
        const float4* erow = (const float4*)(emb + (size_t)v * Dm);
        float acc = 0.0f;
        #pragma unroll
        for (int r = 0; r < 8; r++) {
            float4 e4 = erow[r * 32 + lane];
            float4 h4 = ((float4*)sx)[r * 32 + lane];
            acc += e4.x * h4.x + e4.y * h4.y + e4.z * h4.z + e4.w * h4.w;
        }
        #pragma unroll
        for (int m2 = 16; m2 >= 1; m2 >>= 1)
            acc += __shfl_xor_sync(0xffffffffu, acc, m2);
        if (lane == 0) out[v] = acc;
    }
}

// ---------------- launch ----------------
extern "C" void kernel_launch(void* const* d_in, const int* in_sizes, int n_in,
                              void* d_out, int out_size) {
    mega<<<NB, 256>>>(
        (const int*)d_in[0], (const float*)d_in[1], (const float*)d_in[2],
        (const float*)d_in[3], (const float*)d_in[4], (const float*)d_in[5],
        (const float*)d_in[6], (const float*)d_in[7], (const float*)d_in[8],
        (const float*)d_in[9], (const float*)d_in[10], (const float*)d_in[11],
        (const float*)d_in[12], (const float*)d_in[13], (const float*)d_in[14],
        (const float*)d_in[15], (const float*)d_in[16], (const float*)d_in[17],
        (const float*)d_in[18], (const float*)d_in[19], (const float*)d_in[20],
        (const float*)d_in[21], (const float*)d_in[22], (const float*)d_in[23],
        (float*)d_out);
}

// round 9
// speedup vs baseline: 1.0668x; 1.0668x over previous
#include <cuda_runtime.h>
#include <cstdint>
#include <math.h>

#define Dm 1024
#define Hn 8
#define DHn 128
#define Fn 4096
#define Vn 16384
#define ENCn 438
#define PASTn 447
#define Lnum 8
#define NSPLIT 32
#define SPLEN 14
#define NB 296
#define ATT_SCALE 0.08838834764831845f

// ---------------- device scratch ----------------
__device__ float g_x[Dm];            // residual stream (atomic accumulated)
__device__ float A_qkv[3 * Dm];
__device__ float A_qc[Dm];
__device__ float A_u[Hn * Dm];
__device__ float A_o2[Dm];
__device__ float A_ffn[Fn];
__device__ float g_t[Hn * Dm];
__device__ float g_sc[Hn * ENCn];
__device__ float g_po[Hn * NSPLIT * DHn];
__device__ float g_pm[Hn * NSPLIT];
__device__ float g_ps[Hn * NSPLIT];
__device__ int g_cnt;
__device__ volatile int g_gen;

__device__ __forceinline__ float gelu_f(float v) {
    float c = v * v * v;
    return 0.5f * v * (1.0f + tanhf(0.7978845608028654f * (v + 0.044715f * c)));
}
__device__ __forceinline__ float ldg1(const float* p) { return __ldcg(p); }
__device__ __forceinline__ float4 ldg4(const float* p) { return __ldcg((const float4*)p); }

// ---- cp.async helpers ----
__device__ __forceinline__ void cp16(uint32_t s, const float4* g) {
    asm volatile("cp.async.cg.shared.global [%0], [%1], 16;" :: "r"(s), "l"(g));
}
__device__ __forceinline__ void cp_commit() {
    asm volatile("cp.async.commit_group;");
}
__device__ __forceinline__ void cp_wait0() {
    asm volatile("cp.async.wait_group 0;");
}

// copy W slice [r0 .. r0+rows) x [grp*128 .. +128) into smem buffer
__device__ __forceinline__ void cpW(uint32_t sb, const float* W, int dout4,
                                    int grp, int r0, int rows) {
    const float4* W4 = (const float4*)W;
    int n = rows * 32;
    for (int i = threadIdx.x; i < n; i += 256) {
        int r = i >> 5, c = i & 31;
        cp16(sb + i * 16, W4 + (size_t)(r0 + r) * dout4 + grp * 32 + c);
    }
}

// global software barrier (generation-based; replay-safe; busy spin)
__device__ __forceinline__ void gbar() {
    __syncthreads();
    if (threadIdx.x == 0) {
        __threadfence();
        int gen = g_gen;
        if (atomicAdd(&g_cnt, 1) == NB - 1) {
            g_cnt = 0;
            __threadfence();
            g_gen = gen + 1;
        } else {
            while (g_gen == gen) {}
        }
    }
    __syncthreads();
}

__device__ __forceinline__ void zero1k(float* base) {
    ((float4*)base)[threadIdx.x] = make_float4(0.f, 0.f, 0.f, 0.f);
}

// matvec from smem buffer; atomicAdd 128 outputs into dst[grp*128..)
__device__ __forceinline__ void mv_buf(const float4* buf4, int rows,
                                       const float* sxp, int grp,
                                       float* __restrict__ dst,
                                       float4 (*s_acc)[32]) {
    int tid = threadIdx.x, w = tid >> 5, lane = tid & 31;
    float4 acc = make_float4(0.f, 0.f, 0.f, 0.f);
    #pragma unroll 4
    for (int r = w; r < rows; r += 8) {
        float xv = sxp[r];
        float4 wv = buf4[r * 32 + lane];
        acc.x += xv * wv.x; acc.y += xv * wv.y;
        acc.z += xv * wv.z; acc.w += xv * wv.w;
    }
    s_acc[w][lane] = acc;
    __syncthreads();
    if (tid < 32) {
        float4 t = s_acc[0][tid];
        #pragma unroll
        for (int i = 1; i < 8; i++) {
            float4 a = s_acc[i][tid];
            t.x += a.x; t.y += a.y; t.z += a.z; t.w += a.w;
        }
        float* op = dst + grp * 128 + tid * 4;
        atomicAdd(op + 0, t.x);
        atomicAdd(op + 1, t.y);
        atomicAdd(op + 2, t.z);
        atomicAdd(op + 3, t.w);
    }
    __syncthreads();
}

// LN of g_x -> sx[0..1023]
__device__ __forceinline__ void ln_simple(const float* __restrict__ gamma,
                                          const float* __restrict__ beta,
                                          float* sx, float* swr) {
    int tid = threadIdx.x, w = tid >> 5, lane = tid & 31;
    float4 xv = ldg4(g_x + tid * 4);
    float s = xv.x + xv.y + xv.z + xv.w;
    #pragma unroll
    for (int m = 16; m >= 1; m >>= 1) s += __shfl_xor_sync(0xffffffffu, s, m);
    if (lane == 0) swr[w] = s;
    __syncthreads();
    float mean = 0.0f;
    #pragma unroll
    for (int i = 0; i < 8; i++) mean += swr[i];
    mean *= (1.0f / 1024.0f);
    float4 dv;
    dv.x = xv.x - mean; dv.y = xv.y - mean; dv.z = xv.z - mean; dv.w = xv.w - mean;
    float s2 = dv.x * dv.x + dv.y * dv.y + dv.z * dv.z + dv.w * dv.w;
    #pragma unroll
    for (int m = 16; m >= 1; m >>= 1) s2 += __shfl_xor_sync(0xffffffffu, s2, m);
    __syncthreads();
    if (lane == 0) swr[w] = s2;
    __syncthreads();
    float var = 0.0f;
    #pragma unroll
    for (int i = 0; i < 8; i++) var += swr[i];
    float rstd = rsqrtf(var * (1.0f / 1024.0f) + 1e-5f);
    float4 g4 = ((const float4*)gamma)[tid];
    float4 b4 = ((const float4*)beta)[tid];
    float4 o;
    o.x = dv.x * rstd * g4.x + b4.x;
    o.y = dv.y * rstd * g4.y + b4.y;
    o.z = dv.z * rstd * g4.z + b4.z;
    o.w = dv.w * rstd * g4.w + b4.w;
    ((float4*)sx)[tid] = o;
    __syncthreads();
}

extern __shared__ float dynbuf[];   // 64KB weight staging buffer

__global__ void __launch_bounds__(256, 2)
mega(const int* __restrict__ ids, const float* __restrict__ enc,
     const float* __restrict__ past_k, const float* __restrict__ past_v,
     const float* __restrict__ emb, const float* __restrict__ pos,
     const float* __restrict__ ln1_g, const float* __restrict__ ln1_b,
     const float* __restrict__ wq_s, const float* __restrict__ wk_s,
     const float* __restrict__ wv_s, const float* __restrict__ wo_s,
     const float* __restrict__ ln2_g, const float* __restrict__ ln2_b,
     const float* __restrict__ wq_c, const float* __restrict__ wk_c,
     const float* __restrict__ wv_c, const float* __restrict__ wo_c,
     const float* __restrict__ ln3_g, const float* __restrict__ ln3_b,
     const float* __restrict__ w1, const float* __restrict__ w2,
     const float* __restrict__ lnf_g, const float* __restrict__ lnf_b,
     float* __restrict__ out) {
    __shared__ float sx[8192];
    __shared__ float4 s_acc[8][32];
    __shared__ float swr[8];
    __shared__ float sms[2];
    int bid = blockIdx.x, tid = threadIdx.x, w = tid >> 5, lane = tid & 31;
    const size_t DD = (size_t)Dm * Dm;
    const size_t DF = (size_t)Dm * Fn;
    const size_t KVL = (size_t)Hn * PASTn * DHn;
    float4* buf4 = (float4*)dynbuf;
    uint32_t sb = (uint32_t)__cvta_generic_to_shared(dynbuf);

    // ---- embed + zero accumulators; issue S1(l=0) weights ----
    if (bid == 0) {
        int id = ids[0];
        float4 a = *(const float4*)(emb + (size_t)id * Dm + tid * 4);
        float4 b = *(const float4*)(pos + (size_t)PASTn * Dm + tid * 4);
        a.x += b.x; a.y += b.y; a.z += b.z; a.w += b.w;
        ((float4*)g_x)[tid] = a;
    } else if (bid <= 17) {
        int seg = bid - 1;
        if (seg < 3) zero1k(A_qkv + seg * 1024);
        else if (seg == 3) zero1k(A_qc);
        else if (seg < 12) zero1k(A_u + (seg - 4) * 1024);
        else if (seg == 12) zero1k(A_o2);
        else zero1k(A_ffn + (seg - 13) * 1024);
    }
    if (bid < 288) {
        int m = bid / 96, rem = bid % 96, grp = rem / 12, rs = rem % 12;
        int r0 = (rs * 1024) / 12, rows = ((rs + 1) * 1024) / 12 - r0;
        cpW(sb, (m == 0 ? wq_s : (m == 1 ? wk_s : wv_s)), 256, grp, r0, rows);
    }
    cp_commit();
    gbar();

    for (int l = 0; l < Lnum; l++) {
        const float* pk = past_k + (size_t)l * KVL;
        const float* pv = past_v + (size_t)l * KVL;

        // ==== S1: LN1 + qkv (288 blocks) ====
        if (bid < 288) {
            int m = bid / 96, rem = bid % 96, grp = rem / 12, rs = rem % 12;
            int r0 = (rs * 1024) / 12, rows = ((rs + 1) * 1024) / 12 - r0;
            ln_simple(ln1_g + l * Dm, ln1_b + l * Dm, sx, swr);
            cp_wait0(); __syncthreads();
            mv_buf(buf4, rows, sx + r0, grp, A_qkv + m * Dm, s_acc);
        }
        // issue S2: K/V rows
        if (bid < 256) {
            int h = bid >> 5, split = bid & 31, base = split * SPLEN;
            const float4* K4 = (const float4*)pk;
            const float4* V4 = (const float4*)pv;
            for (int i = tid; i < SPLEN * 32; i += 256) {
                int pp = i >> 5, c = i & 31, p = base + pp;
                if (p < PASTn) {
                    cp16(sb + i * 16, K4 + ((size_t)h * PASTn + p) * 32 + c);
                    cp16(sb + (SPLEN * 32 + i) * 16, V4 + ((size_t)h * PASTn + p) * 32 + c);
                }
            }
        }
        cp_commit();
        gbar();

        // ==== S2: split-KV self attention (256) + zero A_ffn ====
        if (bid < 256) {
            int h = bid >> 5, split = bid & 31, base = split * SPLEN;
            for (int i = tid; i < 384; i += 256) {
                int vec = i >> 7, c = i & 127;
                sx[i] = ldg1(A_qkv + vec * Dm + h * DHn + c);
            }
            __syncthreads();
            cp_wait0(); __syncthreads();
            for (int pp = w; pp < SPLEN; pp += 8) {
                int p = base + pp;
                float4 k4 = (p < PASTn) ? buf4[pp * 32 + lane]
                                        : ((float4*)(sx + 128))[lane];
                float4 q4 = ((float4*)sx)[lane];
                float d = k4.x * q4.x + k4.y * q4.y + k4.z * q4.z + k4.w * q4.w;
                #pragma unroll
                for (int m2 = 16; m2 >= 1; m2 >>= 1)
                    d += __shfl_xor_sync(0xffffffffu, d, m2);
                if (lane == 0) sx[384 + pp] = d * ATT_SCALE;
            }
            __syncthreads();
            if (tid < 32) {
                float v = (lane < SPLEN) ? sx[384 + lane] : -1e30f;
                float mm = v;
                #pragma unroll
                for (int m2 = 16; m2 >= 1; m2 >>= 1)
                    mm = fmaxf(mm, __shfl_xor_sync(0xffffffffu, mm, m2));
                float e = (lane < SPLEN) ? expf(v - mm) : 0.0f;
                float s = e;
                #pragma unroll
                for (int m2 = 16; m2 >= 1; m2 >>= 1)
                    s += __shfl_xor_sync(0xffffffffu, s, m2);
                if (lane < SPLEN) sx[384 + lane] = e;
                if (lane == 0) { sms[0] = mm; sms[1] = s; }
            }
            __syncthreads();
            int c = tid & 127, ph = tid >> 7;
            float acc = 0.0f;
            #pragma unroll
            for (int k = 0; k < 7; k++) {
                int pp = ph * 7 + k;
                int p = base + pp;
                float vv = (p < PASTn) ? dynbuf[SPLEN * 128 + pp * 128 + c]
                                       : sx[256 + c];
                acc += sx[384 + pp] * vv;
            }
            sx[512 + tid] = acc;
            __syncthreads();
            if (tid < 128) {
                g_po[(h * NSPLIT + split) * DHn + tid] = sx[512 + tid] + sx[640 + tid];
                if (tid == 0) {
                    g_pm[h * NSPLIT + split] = sms[0];
                    g_ps[h * NSPLIT + split] = sms[1];
                }
            }
            __syncthreads();
        } else if (bid < 260) {
            zero1k(A_ffn + (bid - 256) * 1024);
        }
        // issue S3: wo_s
        if (bid < 256) cpW(sb, wo_s + l * DD, 256, bid >> 5, (bid & 31) * 32, 32);
        cp_commit();
        gbar();

        // ==== S3: combine + wo_s -> x (256) + zero A_qkv ====
        if (bid < 256) {
            int grp = bid >> 5, rs = bid & 31;
            int h = rs >> 2, c0 = (rs & 3) * 32;
            if (tid < 32) {
                sx[256 + tid] = ldg1(g_pm + h * NSPLIT + tid);
                sx[288 + tid] = ldg1(g_ps + h * NSPLIT + tid);
            }
            __syncthreads();
            if (tid < 32) {
                float M = -1e30f;
                #pragma unroll
                for (int s = 0; s < NSPLIT; s++) M = fmaxf(M, sx[256 + s]);
                float S = 0.0f, o = 0.0f;
                #pragma unroll
                for (int s = 0; s < NSPLIT; s++) {
                    float wv = expf(sx[256 + s] - M);
                    S += sx[288 + s] * wv;
                    o += ldg1(g_po + (h * NSPLIT + s) * DHn + c0 + tid) * wv;
                }
                sx[tid] = o / S;
            }
            __syncthreads();
            cp_wait0(); __syncthreads();
            mv_buf(buf4, 32, sx, grp, g_x, s_acc);
        } else if (bid < 259) {
            zero1k(A_qkv + (bid - 256) * 1024);
        }
        // issue S4: wq_c
        if (bid < 256) cpW(sb, wq_c + l * DD, 256, bid >> 5, (bid & 31) * 32, 32);
        cp_commit();
        gbar();

        // ==== S4: LN2 + qc (256) ====
        if (bid < 256) {
            int grp = bid >> 5, r0 = (bid & 31) * 32;
            ln_simple(ln2_g + l * Dm, ln2_b + l * Dm, sx, swr);
            cp_wait0(); __syncthreads();
            mv_buf(buf4, 32, sx + r0, grp, A_qc, s_acc);
        }
        // issue S5: wk_c rows
        if (bid < 128) {
            const float4* wk4 = (const float4*)(wk_c + l * DD);
            int d0 = bid * 8;
            for (int i = tid; i < 2048; i += 256) {
                int r = i >> 8, c = i & 255;
                cp16(sb + i * 16, wk4 + (size_t)(d0 + r) * 256 + c);
            }
        }
        cp_commit();
        gbar();

        // ==== S5: t (128 blocks, warp per wk row) ====
        if (bid < 128) {
            ((float4*)sx)[tid] = ldg4(A_qc + tid * 4);
            __syncthreads();
            cp_wait0(); __syncthreads();
            int d = bid * 8 + w;
            float acc[Hn];
            #pragma unroll
            for (int h = 0; h < Hn; h++) {
                float4 w4 = buf4[w * 256 + h * 32 + lane];
                float4 q4 = ((float4*)sx)[h * 32 + lane];
                acc[h] = w4.x * q4.x + w4.y * q4.y + w4.z * q4.z + w4.w * q4.w;
            }
            #pragma unroll
            for (int h = 0; h < Hn; h++) {
                #pragma unroll
                for (int m2 = 16; m2 >= 1; m2 >>= 1)
                    acc[h] += __shfl_xor_sync(0xffffffffu, acc[h], m2);
            }
            if (lane == 0) {
                #pragma unroll
                for (int h = 0; h < Hn; h++) g_t[h * Dm + d] = acc[h];
            }
            __syncthreads();
        }
        // issue S6: enc rows
        if (bid < 55) {
            const float4* E4 = (const float4*)enc;
            int e0 = bid * 8;
            for (int i = tid; i < 2048; i += 256) {
                int r = i >> 8, c = i & 255;
                if (e0 + r < ENCn) cp16(sb + i * 16, E4 + (size_t)(e0 + r) * 256 + c);
            }
        }
        cp_commit();
        gbar();

        // ==== S6: cross scores (55) + zero A_qc ====
        if (bid < 55) {
            for (int i = tid; i < 2048; i += 256) ((float4*)sx)[i] = ldg4(g_t + i * 4);
            __syncthreads();
            cp_wait0(); __syncthreads();
            int e = bid * 8 + w;
            if (e < ENCn) {
                float acc[Hn];
                #pragma unroll
                for (int h = 0; h < Hn; h++) acc[h] = 0.0f;
                #pragma unroll
                for (int r = 0; r < 8; r++) {
                    float4 e4 = buf4[w * 256 + r * 32 + lane];
                    #pragma unroll
                    for (int h = 0; h < Hn; h++) {
                        float4 t4 = ((float4*)sx)[h * 256 + r * 32 + lane];
                        acc[h] += e4.x * t4.x + e4.y * t4.y + e4.z * t4.z + e4.w * t4.w;
                    }
                }
                #pragma unroll
                for (int h = 0; h < Hn; h++) {
                    #pragma unroll
                    for (int m2 = 16; m2 >= 1; m2 >>= 1)
                        acc[h] += __shfl_xor_sync(0xffffffffu, acc[h], m2);
                }
                if (lane == 0) {
                    #pragma unroll
                    for (int h = 0; h < Hn; h++)
                        g_sc[h * ENCn + e] = acc[h] * ATT_SCALE;
                }
            }
            __syncthreads();
        } else if (bid == 55) {
            zero1k(A_qc);
        }
        // issue S7: enc slice per (head,grp,rs)
        if (bid < 256) {
            int rem = bid & 31, grp = rem >> 2, rs = rem & 3;
            int ub0 = rs * 110;
            int ub1 = (ub0 + 110 > ENCn) ? ENCn : ub0 + 110;
            cpW(sb, enc, 256, grp, ub0, ub1 - ub0);
        }
        cp_commit();
        gbar();

        // ==== S7: softmax + u (256) ====
        if (bid < 256) {
            int head = bid >> 5, rem = bid & 31, grp = rem >> 2, rs = rem & 3;
            int ub0 = rs * 110;
            int ub1 = (ub0 + 110 > ENCn) ? ENCn : ub0 + 110;
            const float* scp = g_sc + head * ENCn;
            float v0 = (tid < ENCn) ? ldg1(scp + tid) : -1e30f;
            float v1 = (tid + 256 < ENCn) ? ldg1(scp + tid + 256) : -1e30f;
            float m = fmaxf(v0, v1);
            #pragma unroll
            for (int m2 = 16; m2 >= 1; m2 >>= 1)
                m = fmaxf(m, __shfl_xor_sync(0xffffffffu, m, m2));
            if (lane == 0) swr[w] = m;
            __syncthreads();
            float M = swr[0];
            #pragma unroll
            for (int i = 1; i < 8; i++) M = fmaxf(M, swr[i]);
            float e0 = (tid < ENCn) ? expf(v0 - M) : 0.0f;
            float e1 = (tid + 256 < ENCn) ? expf(v1 - M) : 0.0f;
            float s = e0 + e1;
            #pragma unroll
            for (int m2 = 16; m2 >= 1; m2 >>= 1)
                s += __shfl_xor_sync(0xffffffffu, s, m2);
            __syncthreads();
            if (lane == 0) swr[w] = s;
            __syncthreads();
            float S = 0.0f;
            #pragma unroll
            for (int i = 0; i < 8; i++) S += swr[i];
            float inv = 1.0f / S;
            for (int i = tid; i < ub1 - ub0; i += 256)
                sx[i] = expf(ldg1(scp + ub0 + i) - M) * inv;
            __syncthreads();
            cp_wait0(); __syncthreads();
            mv_buf(buf4, ub1 - ub0, sx, grp, A_u + head * Dm, s_acc);
        }
        // issue S8: wv_c
        if (bid < 256) cpW(sb, wv_c + l * DD, 256, bid >> 5, (bid & 31) * 32, 32);
        cp_commit();
        gbar();

        // ==== S8: u @ wv_c -> A_o2 (256) ====
        if (bid < 256) {
            int grp = bid >> 5, r0 = (bid & 31) * 32;
            if (tid < 32) sx[tid] = ldg1(A_u + grp * Dm + r0 + tid);
            __syncthreads();
            cp_wait0(); __syncthreads();
            mv_buf(buf4, 32, sx, grp, A_o2, s_acc);
        }
        // issue S9: wo_c
        if (bid < 256) cpW(sb, wo_c + l * DD, 256, bid >> 5, (bid & 31) * 32, 32);
        cp_commit();
        gbar();

        // ==== S9: o2 @ wo_c -> x (256) + zero A_u ====
        if (bid < 256) {
            int grp = bid >> 5, r0 = (bid & 31) * 32;
            if (tid < 32) sx[tid] = ldg1(A_o2 + r0 + tid);
            __syncthreads();
            cp_wait0(); __syncthreads();
            mv_buf(buf4, 32, sx, grp, g_x, s_acc);
        } else if (bid < 264) {
            zero1k(A_u + (bid - 256) * 1024);
        }
        // issue S10: w1 (128-row slices)
        if (bid < 256) cpW(sb, w1 + l * DF, 1024, bid >> 3, (bid & 7) * 128, 128);
        cp_commit();
        gbar();

        // ==== S10: LN3 + w1 -> A_ffn (256) + zero A_o2 ====
        if (bid < 256) {
            int grp = bid >> 3, r0 = (bid & 7) * 128;
            ln_simple(ln3_g + l * Dm, ln3_b + l * Dm, sx, swr);
            cp_wait0(); __syncthreads();
            mv_buf(buf4, 128, sx + r0, grp, A_ffn, s_acc);
        } else if (bid == 256) {
            zero1k(A_o2);
        }
        // issue S11: w2 (128-row slices)
        if (bid < 256) cpW(sb, w2 + l * DF, 256, bid >> 5, (bid & 31) * 128, 128);
        cp_commit();
        gbar();

        // ==== S11: gelu(ffn) @ w2 -> x (256) ====
        if (bid < 256) {
            int grp = bid >> 5, r0 = (bid & 31) * 128;
            if (tid < 128) sx[tid] = gelu_f(ldg1(A_ffn + r0 + tid));
            __syncthreads();
            cp_wait0(); __syncthreads();
            mv_buf(buf4, 128, sx, grp, g_x, s_acc);
        }
        // issue next layer's S1
        if (l < Lnum - 1 && bid < 288) {
            int m = bid / 96, rem = bid % 96, grp = rem / 12, rs = rem % 12;
            int r0 = (rs * 1024) / 12, rows = ((rs + 1) * 1024) / 12 - r0;
            cpW(sb, (m == 0 ? wq_s : (m == 1 ? wk_s : wv_s)) + (l + 1) * DD,
                256, grp, r0, rows);
        }
        cp_commit();
        gbar();
    }

    // ---- final LN + tied lm_head (direct streaming) ----
    ln_simple(lnf_g, lnf_b, sx, swr);
    for (int v = bid * 8 + w; v < Vn; v += NB * 8) {
        const float4* erow = (const float4*)(emb + (size_t)v * Dm);
        float acc = 0.0f;
        #pragma unroll
        for (int r = 0; r < 8; r++) {
            float4 e4 = erow[r * 32 + lane];
            float4 h4 = ((float4*)sx)[r * 32 + lane];
            acc += e4.x * h4.x + e4.y * h4.y + e4.z * h4.z + e4.w * h4.w;
        }
        #pragma unroll
        for (int m2 = 16; m2 >= 1; m2 >>= 1)
            acc += __shfl_xor_sync(0xffffffffu, acc, m2);
        if (lane == 0) out[v] = acc;
    }
}

// ---------------- launch ----------------
extern "C" void kernel_launch(void* const* d_in, const int* in_sizes, int n_in,
                              void* d_out, int out_size) {
    cudaFuncSetAttribute(mega, cudaFuncAttributeMaxDynamicSharedMemorySize, 65536);
    mega<<<NB, 256, 65536>>>(
        (const int*)d_in[0], (const float*)d_in[1], (const float*)d_in[2],
        (const float*)d_in[3], (const float*)d_in[4], (const float*)d_in[5],
        (const float*)d_in[6], (const float*)d_in[7], (const float*)d_in[8],
        (const float*)d_in[9], (const float*)d_in[10], (const float*)d_in[11],
        (const float*)d_in[12], (const float*)d_in[13], (const float*)d_in[14],
        (const float*)d_in[15], (const float*)d_in[16], (const float*)d_in[17],
        (const float*)d_in[18], (const float*)d_in[19], (const float*)d_in[20],
        (const float*)d_in[21], (const float*)d_in[22], (const float*)d_in[23],
        (float*)d_out);
}